// round 12
// baseline (speedup 1.0000x reference)
#include <cuda_runtime.h>
#include <cuda_bf16.h>
#include <cuda_fp16.h>
#include <cstdint>
#include <math.h>

// ---------------------------------------------------------------------------
// Problem constants
// ---------------------------------------------------------------------------
#define B_  2
#define T_  2048
#define E_  128
#define H_  8
#define HS_ 16
#define HID_ 65536
#define NTOK (B_ * T_)          // 4096
#define EPS_ 1e-5f
#define ATT_SCALE 0.08838834764831845f   // 1/sqrt(128)

// FFN tiling (1-pass fp16, JC=64, 1024 threads)
#define FFN_M 128
#define JC2 64
#define NCHUNK2 (HID_ / JC2)        // 1024 chunks per tile
#define NTILE (NTOK / FFN_M)        // 32
#define TOT2 (NTILE * NCHUNK2)      // 32768
#define FFN_GRID 444                // 3 * 148 SMs, perfect waves

// padded smem strides (in halves); stride*2 bytes/16 must be odd for ldmatrix
#define SH   136   // h / generic 128-col tiles (17 x 16B)
#define SWN  72    // 64-col tiles: W1 chunk, act (9 x 16B)
#define SW2  136   // W2 chunk 128-col

// FFN smem byte offsets
#define G2_H 0                            // 128 x 136 x 2 = 34816
#define G2_W1(b) (34816 + (b) * 18432)    // 128 x 72 x 2
#define G2_W2(b) (71680 + (b) * 17408)    // 64 x 136 x 2
#define G2_AC 106496                      // 128 x 72 x 2
#define FFN_SMEM3 124928

// QKV / OPROJ GEMM smem offsets (bf16 3-pass path, unchanged)
#define GA_HI 0
#define GA_LO 17408
#define GW_HI 34816
#define GW_LO 69632
#define QKV_SMEM 104448
#define OP_X2T  104448
#define OP_SMEM (104448 + 64 * 132 * 4)

// ---------------------------------------------------------------------------
// PTX helpers
// ---------------------------------------------------------------------------
__device__ __forceinline__ uint32_t smem_u32(const void* p) {
    uint32_t a;
    asm("{ .reg .u64 t; cvta.to.shared.u64 t, %1; cvt.u32.u64 %0, t; }"
        : "=r"(a) : "l"(p));
    return a;
}
__device__ __forceinline__ void ldsm4(uint32_t a[4], uint32_t addr) {
    asm volatile("ldmatrix.sync.aligned.m8n8.x4.shared.b16 {%0,%1,%2,%3}, [%4];"
                 : "=r"(a[0]), "=r"(a[1]), "=r"(a[2]), "=r"(a[3]) : "r"(addr));
}
__device__ __forceinline__ void ldsm4t(uint32_t a[4], uint32_t addr) {
    asm volatile("ldmatrix.sync.aligned.m8n8.x4.trans.shared.b16 {%0,%1,%2,%3}, [%4];"
                 : "=r"(a[0]), "=r"(a[1]), "=r"(a[2]), "=r"(a[3]) : "r"(addr));
}
__device__ __forceinline__ void mma16816(float c[4], const uint32_t a[4],
                                         const uint32_t b[2]) {
    asm volatile("mma.sync.aligned.m16n8k16.row.col.f32.bf16.bf16.f32 "
                 "{%0,%1,%2,%3}, {%4,%5,%6,%7}, {%8,%9}, {%0,%1,%2,%3};"
                 : "+f"(c[0]), "+f"(c[1]), "+f"(c[2]), "+f"(c[3])
                 : "r"(a[0]), "r"(a[1]), "r"(a[2]), "r"(a[3]),
                   "r"(b[0]), "r"(b[1]));
}
__device__ __forceinline__ void mma16816h(float c[4], const uint32_t a[4],
                                          const uint32_t b[2]) {
    asm volatile("mma.sync.aligned.m16n8k16.row.col.f32.f16.f16.f32 "
                 "{%0,%1,%2,%3}, {%4,%5,%6,%7}, {%8,%9}, {%0,%1,%2,%3};"
                 : "+f"(c[0]), "+f"(c[1]), "+f"(c[2]), "+f"(c[3])
                 : "r"(a[0]), "r"(a[1]), "r"(a[2]), "r"(a[3]),
                   "r"(b[0]), "r"(b[1]));
}
__device__ __forceinline__ void cp16(uint32_t s, const void* g) {
    asm volatile("cp.async.cg.shared.global [%0], [%1], 16;" :: "r"(s), "l"(g));
}
#define CP_COMMIT() asm volatile("cp.async.commit_group;" ::: "memory")
#define CP_WAIT1()  asm volatile("cp.async.wait_group 1;" ::: "memory")

__device__ __forceinline__ uint32_t pack_bf16(float a, float b) {
    uint32_t ua = __bfloat16_as_ushort(__float2bfloat16(a));
    uint32_t ub = __bfloat16_as_ushort(__float2bfloat16(b));
    return ua | (ub << 16);
}
__device__ __forceinline__ uint32_t pack_f16(float a, float b) {
    __half2 h = __floats2half2_rn(a, b);
    return *reinterpret_cast<uint32_t*>(&h);
}

// ---------------------------------------------------------------------------
// Scratch
// ---------------------------------------------------------------------------
__device__ float g_q  [B_ * H_ * T_ * HS_];
__device__ float g_k  [B_ * H_ * T_ * HS_];
__device__ float g_v  [B_ * H_ * T_ * HS_];
__device__ float g_x2 [NTOK * E_];
__device__ float g_part2[2 * FFN_GRID * FFN_M * E_];
__device__ __nv_bfloat16 g_h1hi[NTOK * E_];
__device__ __nv_bfloat16 g_h1lo[NTOK * E_];
__device__ __nv_bfloat16 g_aohi[NTOK * E_];
__device__ __nv_bfloat16 g_aolo[NTOK * E_];
__device__ __half g_h2f [NTOK * E_];
__device__ __half g_w1f [E_ * HID_];
__device__ __half g_w2f [HID_ * E_];
__device__ __nv_bfloat16 g_wqkvhi[E_ * 384];
__device__ __nv_bfloat16 g_wqkvlo[E_ * 384];
__device__ __nv_bfloat16 g_wohi[E_ * E_];
__device__ __nv_bfloat16 g_wolo[E_ * E_];

// ---------------------------------------------------------------------------
// fp32 -> bf16 hi/lo split (attention-path weights)
// ---------------------------------------------------------------------------
__global__ void k_cvt(const float* __restrict__ src,
                      __nv_bfloat16* __restrict__ hi,
                      __nv_bfloat16* __restrict__ lo, int n4) {
    int i = blockIdx.x * 256 + threadIdx.x;
    if (i >= n4) return;
    float4 v = ((const float4*)src)[i];
    __nv_bfloat16 h0 = __float2bfloat16(v.x), h1 = __float2bfloat16(v.y);
    __nv_bfloat16 h2 = __float2bfloat16(v.z), h3 = __float2bfloat16(v.w);
    uint2 ho, loo;
    ho.x = ((uint32_t)__bfloat16_as_ushort(h1) << 16) | __bfloat16_as_ushort(h0);
    ho.y = ((uint32_t)__bfloat16_as_ushort(h3) << 16) | __bfloat16_as_ushort(h2);
    loo.x = pack_bf16(v.x - __bfloat162float(h0), v.y - __bfloat162float(h1));
    loo.y = pack_bf16(v.z - __bfloat162float(h2), v.w - __bfloat162float(h3));
    ((uint2*)hi)[i] = ho;
    ((uint2*)lo)[i] = loo;
}

// fp32 -> fp16 plain convert (FFN weights)
__global__ void k_cvthalf(const float* __restrict__ src,
                          __half* __restrict__ dst, int n4) {
    int i = blockIdx.x * 256 + threadIdx.x;
    if (i >= n4) return;
    float4 v = ((const float4*)src)[i];
    uint2 o;
    o.x = pack_f16(v.x, v.y);
    o.y = pack_f16(v.z, v.w);
    ((uint2*)dst)[i] = o;
}

// Build Wqkv [E][384] bf16 hi/lo from Wq/Wk/Wv [H][E][HS]
__global__ void k_prep_wqkv(const float* __restrict__ Wq, const float* __restrict__ Wk,
                            const float* __restrict__ Wv,
                            __nv_bfloat16* __restrict__ ohi,
                            __nv_bfloat16* __restrict__ olo) {
    int idx = blockIdx.x * 256 + threadIdx.x;
    if (idx >= E_ * 384) return;
    int e = idx / 384, n = idx % 384;
    int which = n >> 7, r = n & 127, h = r >> 4, hd = r & 15;
    const float* W = (which == 0) ? Wq : (which == 1) ? Wk : Wv;
    float f = W[((size_t)h * E_ + e) * HS_ + hd];
    __nv_bfloat16 hh = __float2bfloat16(f);
    ohi[idx] = hh;
    olo[idx] = __float2bfloat16(f - __bfloat162float(hh));
}

// ---------------------------------------------------------------------------
// LayerNorm with bf16 hi/lo split output (LN1)
// ---------------------------------------------------------------------------
__global__ void k_ln_split(const float* __restrict__ x, const float* __restrict__ g,
                           const float* __restrict__ b,
                           __nv_bfloat16* __restrict__ ohi,
                           __nv_bfloat16* __restrict__ olo) {
    int t = blockIdx.x * 4 + (threadIdx.x >> 5);
    int lane = threadIdx.x & 31;
    float4 a = ((const float4*)(x + (size_t)t * E_))[lane];

    float s = a.x + a.y + a.z + a.w;
    #pragma unroll
    for (int o = 16; o; o >>= 1) s += __shfl_xor_sync(0xffffffffu, s, o);
    float mu = s * (1.0f / E_);

    float dx = a.x - mu, dy = a.y - mu, dz = a.z - mu, dw = a.w - mu;
    float v = dx*dx + dy*dy + dz*dz + dw*dw;
    #pragma unroll
    for (int o = 16; o; o >>= 1) v += __shfl_xor_sync(0xffffffffu, v, o);
    float rs = rsqrtf(v * (1.0f / E_) + EPS_);

    float4 gg = ((const float4*)g)[lane];
    float4 bb = ((const float4*)b)[lane];
    float r0 = dx * rs * gg.x + bb.x;
    float r1 = dy * rs * gg.y + bb.y;
    float r2 = dz * rs * gg.z + bb.z;
    float r3 = dw * rs * gg.w + bb.w;

    __nv_bfloat16 h0 = __float2bfloat16(r0), h1 = __float2bfloat16(r1);
    __nv_bfloat16 h2 = __float2bfloat16(r2), h3 = __float2bfloat16(r3);
    uint2 ho, loo;
    ho.x = ((uint32_t)__bfloat16_as_ushort(h1) << 16) | __bfloat16_as_ushort(h0);
    ho.y = ((uint32_t)__bfloat16_as_ushort(h3) << 16) | __bfloat16_as_ushort(h2);
    loo.x = pack_bf16(r0 - __bfloat162float(h0), r1 - __bfloat162float(h1));
    loo.y = pack_bf16(r2 - __bfloat162float(h2), r3 - __bfloat162float(h3));
    ((uint2*)(ohi + (size_t)t * E_))[lane] = ho;
    ((uint2*)(olo + (size_t)t * E_))[lane] = loo;
}

// ---------------------------------------------------------------------------
// QKV via mma (bf16 3-pass, unchanged)
// ---------------------------------------------------------------------------
__global__ void __launch_bounds__(256, 1)
k_qkv_mma(const __nv_bfloat16* __restrict__ ahi, const __nv_bfloat16* __restrict__ alo,
          const __nv_bfloat16* __restrict__ whi, const __nv_bfloat16* __restrict__ wlo,
          float* __restrict__ q, float* __restrict__ k, float* __restrict__ v) {
    extern __shared__ char smem[];
    const uint32_t sb = smem_u32(smem);
    const int tid = threadIdx.x, wid = tid >> 5, lane = tid & 31;
    const int gid = lane >> 2, tig = lane & 3;
    const int lrow = (lane & 7) + ((lane >> 3) & 1) * 8;
    const int lcol = ((lane >> 4) & 1) * 8;
    const int wm = wid & 1, wn = wid >> 1;
    const int tok0 = blockIdx.x * 64;
    const int slab = blockIdx.y;
    const int m0 = wm * 32, n0 = wn * 32;

    for (int i = tid; i < 1024; i += 256) {
        int r = i >> 4, s = i & 15;
        *(float4*)(smem + GA_HI + (r * SH + s * 8) * 2) =
            *(const float4*)(ahi + (size_t)(tok0 + r) * E_ + s * 8);
        *(float4*)(smem + GA_LO + (r * SH + s * 8) * 2) =
            *(const float4*)(alo + (size_t)(tok0 + r) * E_ + s * 8);
    }
    for (int i = tid; i < 2048; i += 256) {
        int r = i >> 4, s = i & 15;
        *(float4*)(smem + GW_HI + (r * SH + s * 8) * 2) =
            *(const float4*)(whi + (size_t)r * 384 + slab * 128 + s * 8);
        *(float4*)(smem + GW_LO + (r * SH + s * 8) * 2) =
            *(const float4*)(wlo + (size_t)r * 384 + slab * 128 + s * 8);
    }
    __syncthreads();

    float acc[2][4][4];
    #pragma unroll
    for (int a = 0; a < 2; ++a)
        #pragma unroll
        for (int b = 0; b < 4; ++b)
            #pragma unroll
            for (int c = 0; c < 4; ++c) acc[a][b][c] = 0.f;

    #pragma unroll
    for (int kf = 0; kf < 8; ++kf) {
        const int k0 = kf * 16;
        uint32_t ah[2][4], al[2][4], bh2[2][4], bl2[2][4];
        #pragma unroll
        for (int mi = 0; mi < 2; ++mi) {
            uint32_t ro = (uint32_t)((m0 + mi * 16 + lrow) * SH + k0 + lcol) * 2;
            ldsm4(ah[mi], sb + GA_HI + ro);
            ldsm4(al[mi], sb + GA_LO + ro);
        }
        #pragma unroll
        for (int g = 0; g < 2; ++g) {
            uint32_t ro = (uint32_t)((k0 + lrow) * SH + n0 + g * 16 + lcol) * 2;
            ldsm4t(bh2[g], sb + GW_HI + ro);
            ldsm4t(bl2[g], sb + GW_LO + ro);
        }
        #pragma unroll
        for (int mi = 0; mi < 2; ++mi)
            #pragma unroll
            for (int g = 0; g < 2; ++g)
                #pragma unroll
                for (int hh = 0; hh < 2; ++hh) {
                    float* a = acc[mi][g * 2 + hh];
                    mma16816(a, ah[mi], &bh2[g][hh * 2]);
                    mma16816(a, ah[mi], &bl2[g][hh * 2]);
                    mma16816(a, al[mi], &bh2[g][hh * 2]);
                }
    }

    float* dst = (slab == 0) ? q : (slab == 1) ? k : v;
    #pragma unroll
    for (int mi = 0; mi < 2; ++mi) {
        int tg = tok0 + m0 + mi * 16 + gid;
        int b = tg >> 11, tl = tg & 2047;
        #pragma unroll
        for (int ni = 0; ni < 4; ++ni) {
            int n = n0 + ni * 8 + tig * 2;
            int h = n >> 4, hd = n & 15;
            float* p = dst + (((size_t)(b * 8 + h)) * T_ + tl) * HS_ + hd;
            *(float2*)p = make_float2(acc[mi][ni][0], acc[mi][ni][1]);
            *(float2*)(p + 8 * HS_) = make_float2(acc[mi][ni][2], acc[mi][ni][3]);
        }
    }
}

// ---------------------------------------------------------------------------
// Attention (unchanged)
// ---------------------------------------------------------------------------
__global__ void __launch_bounds__(256, 1)
k_attn2(const float* __restrict__ q, const float* __restrict__ k,
        const float* __restrict__ v,
        __nv_bfloat16* __restrict__ aohi, __nv_bfloat16* __restrict__ aolo) {
    __shared__ float Ks[2][128][16];
    __shared__ float Vs[2][128][16];
    const int tid = threadIdx.x, wid = tid >> 5, lane = tid & 31;
    const int bh = blockIdx.y, qb = blockIdx.x;
    const int wg = wid >> 2;
    const int qblk = wg ? (15 - qb) : qb;
    const int t = qblk * 128 + (wid & 3) * 32 + lane;
    const int mytiles = qblk + 1;
    const int ntiles = 16 - qb;

    const float* qp = q + ((size_t)bh * T_ + t) * HS_;
    float4 q0 = ((const float4*)qp)[0];
    float4 q1 = ((const float4*)qp)[1];
    float4 q2 = ((const float4*)qp)[2];
    float4 q3 = ((const float4*)qp)[3];
    const float* kb_ = k + (size_t)bh * T_ * HS_;
    const float* vb_ = v + (size_t)bh * T_ * HS_;
    const uint32_t ksa = smem_u32(Ks), vsa = smem_u32(Vs);

    float m = -1e30f, l = 0.f;
    float o[16];
    #pragma unroll
    for (int d = 0; d < 16; ++d) o[d] = 0.f;

    #pragma unroll
    for (int i = 0; i < 2; ++i) {
        int f = tid + i * 256;
        int row = f >> 2, sg = f & 3;
        cp16(ksa + row * 64 + sg * 16, kb_ + (size_t)row * HS_ + sg * 4);
        cp16(vsa + row * 64 + sg * 16, vb_ + (size_t)row * HS_ + sg * 4);
    }
    CP_COMMIT();

    for (int it = 0; it < ntiles; ++it) {
        const int buf = it & 1;
        if (it + 1 < ntiles) {
            int kb2 = (it + 1) * 128;
            int ob = (buf ^ 1) * 8192;
            #pragma unroll
            for (int i = 0; i < 2; ++i) {
                int f = tid + i * 256;
                int row = f >> 2, sg = f & 3;
                cp16(ksa + ob + row * 64 + sg * 16, kb_ + (size_t)(kb2 + row) * HS_ + sg * 4);
                cp16(vsa + ob + row * 64 + sg * 16, vb_ + (size_t)(kb2 + row) * HS_ + sg * 4);
            }
        }
        CP_COMMIT();
        CP_WAIT1();
        __syncthreads();

        if (it < mytiles) {
            const int kbase = it * 128;
            #pragma unroll 2
            for (int j = 0; j < 128; ++j) {
                const float4* kr = (const float4*)&Ks[buf][j][0];
                float4 k0 = kr[0], k1 = kr[1], k2 = kr[2], k3 = kr[3];
                float sc = q0.x*k0.x + q0.y*k0.y + q0.z*k0.z + q0.w*k0.w
                         + q1.x*k1.x + q1.y*k1.y + q1.z*k1.z + q1.w*k1.w
                         + q2.x*k2.x + q2.y*k2.y + q2.z*k2.z + q2.w*k2.w
                         + q3.x*k3.x + q3.y*k3.y + q3.z*k3.z + q3.w*k3.w;
                sc *= ATT_SCALE;
                if (kbase + j > t) sc = -1e30f;
                float mn = fmaxf(m, sc);
                float scale = __expf(m - mn);
                float w = __expf(sc - mn);
                l = l * scale + w;
                const float4* vr = (const float4*)&Vs[buf][j][0];
                float4 v0 = vr[0], v1 = vr[1], v2 = vr[2], v3 = vr[3];
                o[0]  = o[0]*scale  + w*v0.x;  o[1]  = o[1]*scale  + w*v0.y;
                o[2]  = o[2]*scale  + w*v0.z;  o[3]  = o[3]*scale  + w*v0.w;
                o[4]  = o[4]*scale  + w*v1.x;  o[5]  = o[5]*scale  + w*v1.y;
                o[6]  = o[6]*scale  + w*v1.z;  o[7]  = o[7]*scale  + w*v1.w;
                o[8]  = o[8]*scale  + w*v2.x;  o[9]  = o[9]*scale  + w*v2.y;
                o[10] = o[10]*scale + w*v2.z;  o[11] = o[11]*scale + w*v2.w;
                o[12] = o[12]*scale + w*v3.x;  o[13] = o[13]*scale + w*v3.y;
                o[14] = o[14]*scale + w*v3.z;  o[15] = o[15]*scale + w*v3.w;
                m = mn;
            }
        }
        __syncthreads();
    }

    float inv = 1.0f / l;
    int b = bh >> 3, h = bh & 7;
    size_t base = ((size_t)b * T_ + t) * E_ + h * HS_;
    uint32_t hi[8], lo[8];
    #pragma unroll
    for (int d = 0; d < 8; ++d) {
        float f0 = o[2 * d] * inv, f1 = o[2 * d + 1] * inv;
        __nv_bfloat16 h0 = __float2bfloat16(f0), h1 = __float2bfloat16(f1);
        hi[d] = ((uint32_t)__bfloat16_as_ushort(h1) << 16) | __bfloat16_as_ushort(h0);
        lo[d] = pack_bf16(f0 - __bfloat162float(h0), f1 - __bfloat162float(h1));
    }
    ((uint4*)(aohi + base))[0] = make_uint4(hi[0], hi[1], hi[2], hi[3]);
    ((uint4*)(aohi + base))[1] = make_uint4(hi[4], hi[5], hi[6], hi[7]);
    ((uint4*)(aolo + base))[0] = make_uint4(lo[0], lo[1], lo[2], lo[3]);
    ((uint4*)(aolo + base))[1] = make_uint4(lo[4], lo[5], lo[6], lo[7]);
}

// ---------------------------------------------------------------------------
// O-proj via mma + residual + fused LN2 (h2 fp16 out)
// ---------------------------------------------------------------------------
__global__ void __launch_bounds__(256, 1)
k_oproj_mma(const __nv_bfloat16* __restrict__ ahi, const __nv_bfloat16* __restrict__ alo,
            const __nv_bfloat16* __restrict__ whi, const __nv_bfloat16* __restrict__ wlo,
            const float* __restrict__ bo, const float* __restrict__ x,
            const float* __restrict__ g2, const float* __restrict__ be2,
            float* __restrict__ x2, __half* __restrict__ h2f) {
    extern __shared__ char smem[];
    const uint32_t sb = smem_u32(smem);
    float* x2t = (float*)(smem + OP_X2T);
    const int tid = threadIdx.x, wid = tid >> 5, lane = tid & 31;
    const int gid = lane >> 2, tig = lane & 3;
    const int lrow = (lane & 7) + ((lane >> 3) & 1) * 8;
    const int lcol = ((lane >> 4) & 1) * 8;
    const int wm = wid & 1, wn = wid >> 1;
    const int tok0 = blockIdx.x * 64;
    const int m0 = wm * 32, n0 = wn * 32;

    for (int i = tid; i < 1024; i += 256) {
        int r = i >> 4, s = i & 15;
        *(float4*)(smem + GA_HI + (r * SH + s * 8) * 2) =
            *(const float4*)(ahi + (size_t)(tok0 + r) * E_ + s * 8);
        *(float4*)(smem + GA_LO + (r * SH + s * 8) * 2) =
            *(const float4*)(alo + (size_t)(tok0 + r) * E_ + s * 8);
    }
    for (int i = tid; i < 2048; i += 256) {
        int r = i >> 4, s = i & 15;
        *(float4*)(smem + GW_HI + (r * SH + s * 8) * 2) =
            *(const float4*)(whi + (size_t)r * E_ + s * 8);
        *(float4*)(smem + GW_LO + (r * SH + s * 8) * 2) =
            *(const float4*)(wlo + (size_t)r * E_ + s * 8);
    }
    __syncthreads();

    float acc[2][4][4];
    #pragma unroll
    for (int a = 0; a < 2; ++a)
        #pragma unroll
        for (int b = 0; b < 4; ++b)
            #pragma unroll
            for (int c = 0; c < 4; ++c) acc[a][b][c] = 0.f;

    #pragma unroll
    for (int kf = 0; kf < 8; ++kf) {
        const int k0 = kf * 16;
        uint32_t ah[2][4], al[2][4], bh2[2][4], bl2[2][4];
        #pragma unroll
        for (int mi = 0; mi < 2; ++mi) {
            uint32_t ro = (uint32_t)((m0 + mi * 16 + lrow) * SH + k0 + lcol) * 2;
            ldsm4(ah[mi], sb + GA_HI + ro);
            ldsm4(al[mi], sb + GA_LO + ro);
        }
        #pragma unroll
        for (int g = 0; g < 2; ++g) {
            uint32_t ro = (uint32_t)((k0 + lrow) * SH + n0 + g * 16 + lcol) * 2;
            ldsm4t(bh2[g], sb + GW_HI + ro);
            ldsm4t(bl2[g], sb + GW_LO + ro);
        }
        #pragma unroll
        for (int mi = 0; mi < 2; ++mi)
            #pragma unroll
            for (int g = 0; g < 2; ++g)
                #pragma unroll
                for (int hh = 0; hh < 2; ++hh) {
                    float* a = acc[mi][g * 2 + hh];
                    mma16816(a, ah[mi], &bh2[g][hh * 2]);
                    mma16816(a, ah[mi], &bl2[g][hh * 2]);
                    mma16816(a, al[mi], &bh2[g][hh * 2]);
                }
    }

    #pragma unroll
    for (int mi = 0; mi < 2; ++mi) {
        int rl = m0 + mi * 16 + gid;
        #pragma unroll
        for (int ni = 0; ni < 4; ++ni) {
            int col = n0 + ni * 8 + tig * 2;
            float2 bia = *(const float2*)(bo + col);
            float2 xr0 = *(const float2*)(x + (size_t)(tok0 + rl) * E_ + col);
            float2 xr1 = *(const float2*)(x + (size_t)(tok0 + rl + 8) * E_ + col);
            x2t[rl * 132 + col]           = acc[mi][ni][0] + bia.x + xr0.x;
            x2t[rl * 132 + col + 1]       = acc[mi][ni][1] + bia.y + xr0.y;
            x2t[(rl + 8) * 132 + col]     = acc[mi][ni][2] + bia.x + xr1.x;
            x2t[(rl + 8) * 132 + col + 1] = acc[mi][ni][3] + bia.y + xr1.y;
        }
    }
    __syncthreads();

    float4 gg = ((const float4*)g2)[lane];
    float4 bb = ((const float4*)be2)[lane];
    #pragma unroll
    for (int r = 0; r < 8; ++r) {
        int tokl = wid * 8 + r;
        float4 a = *(float4*)(x2t + tokl * 132 + lane * 4);
        float s = a.x + a.y + a.z + a.w;
        #pragma unroll
        for (int o = 16; o; o >>= 1) s += __shfl_xor_sync(0xffffffffu, s, o);
        float mu = s * (1.0f / E_);
        float dx = a.x - mu, dy = a.y - mu, dz = a.z - mu, dw = a.w - mu;
        float vv = dx*dx + dy*dy + dz*dz + dw*dw;
        #pragma unroll
        for (int o = 16; o; o >>= 1) vv += __shfl_xor_sync(0xffffffffu, vv, o);
        float rs = rsqrtf(vv * (1.0f / E_) + EPS_);

        ((float4*)(x2 + (size_t)(tok0 + tokl) * E_))[lane] = a;

        float r0 = dx * rs * gg.x + bb.x;
        float r1 = dy * rs * gg.y + bb.y;
        float r2 = dz * rs * gg.z + bb.z;
        float r3 = dw * rs * gg.w + bb.w;
        uint2 hp;
        hp.x = pack_f16(r0, r1);
        hp.y = pack_f16(r2, r3);
        ((uint2*)(h2f + (size_t)(tok0 + tokl) * E_))[lane] = hp;
    }
}

// ---------------------------------------------------------------------------
// FFN fp16 1-pass, JC=64, 1024 threads (32 warps, 8/SMSP), balanced 444 CTAs
// Warp grid: wm = wid & 7 (8 x 16 rows), wn = wid >> 3 (4 N-groups)
// ---------------------------------------------------------------------------
__global__ void __launch_bounds__(1024, 1)
k_ffn3(const __half* __restrict__ h2,
       const __half* __restrict__ w1, const __half* __restrict__ w2,
       const float* __restrict__ bf1, float* __restrict__ partial) {
    extern __shared__ char smem[];
    const uint32_t sb = smem_u32(smem);
    const int tid = threadIdx.x, wid = tid >> 5, lane = tid & 31;
    const int gid = lane >> 2, tig = lane & 3;
    const int lrow = (lane & 7) + ((lane >> 3) & 1) * 8;
    const int lcol = ((lane >> 4) & 1) * 8;
    const int wm = wid & 7, wn = wid >> 3;   // 8 x 4 warp grid
    const int m0 = wm * 16;
    const int cta = blockIdx.x;
    const int u0 = (int)(((long long)cta * TOT2) / FFN_GRID);
    const int u1 = (int)(((long long)(cta + 1) * TOT2) / FFN_GRID);

    // prefetch W(u0) -> buf 0 (W1 chunk 128x64, W2 chunk 64x128); 1 iter each
    {
        int jb = (u0 & (NCHUNK2 - 1)) * JC2;
        int e = tid >> 3, sg = tid & 7;
        cp16(sb + G2_W1(0) + (e * SWN + sg * 8) * 2, w1 + (size_t)e * HID_ + jb + sg * 8);
        int j = tid >> 4, sg2 = tid & 15;
        cp16(sb + G2_W2(0) + (j * SW2 + sg2 * 8) * 2, w2 + (size_t)(jb + j) * E_ + sg2 * 8);
    }
    CP_COMMIT();

    int u = u0, seg = 0;
    while (u < u1) {
        const int tile = u >> 10;
        const int useg_end = min(u1, (tile + 1) << 10);
        const int tok0 = tile * FFN_M;

        // load h tile (fp16)
        for (int i = tid; i < 2048; i += 1024) {
            int r = i >> 4, s = i & 15;
            *(float4*)(smem + G2_H + (r * SH + s * 8) * 2) =
                *(const float4*)(h2 + (size_t)(tok0 + r) * E_ + s * 8);
        }
        float acc2[4][4];
        #pragma unroll
        for (int b = 0; b < 4; ++b)
            #pragma unroll
            for (int c = 0; c < 4; ++c) acc2[b][c] = 0.f;
        __syncthreads();

        for (; u < useg_end; ++u) {
            const int buf = (u - u0) & 1;
            const int jb = (u & (NCHUNK2 - 1)) * JC2;

            if (u + 1 < u1) {
                int jn = ((u + 1) & (NCHUNK2 - 1)) * JC2;
                int e = tid >> 3, sg = tid & 7;
                cp16(sb + G2_W1(buf ^ 1) + (e * SWN + sg * 8) * 2,
                     w1 + (size_t)e * HID_ + jn + sg * 8);
                int j = tid >> 4, sg2 = tid & 15;
                cp16(sb + G2_W2(buf ^ 1) + (j * SW2 + sg2 * 8) * 2,
                     w2 + (size_t)(jn + j) * E_ + sg2 * 8);
            }
            CP_COMMIT();
            CP_WAIT1();
            __syncthreads();

            // GEMM1: act[128][64] = relu(h @ W1chunk + b1); warp: 16M x 16N
            const int n1 = wn * 16;
            float acc1[2][4];
            #pragma unroll
            for (int b = 0; b < 2; ++b)
                #pragma unroll
                for (int d = 0; d < 4; ++d) acc1[b][d] = 0.f;

            #pragma unroll
            for (int kf = 0; kf < 8; ++kf) {
                const int k0 = kf * 16;
                uint32_t af[4], bq[4];
                {
                    uint32_t ro = (uint32_t)((m0 + lrow) * SH + k0 + lcol) * 2;
                    ldsm4(af, sb + G2_H + ro);
                }
                {
                    uint32_t ro = (uint32_t)((k0 + lrow) * SWN + n1 + lcol) * 2;
                    ldsm4t(bq, sb + G2_W1(buf) + ro);
                }
                #pragma unroll
                for (int ni = 0; ni < 2; ++ni)
                    mma16816h(acc1[ni], af, &bq[ni * 2]);
            }

            // epilogue: bias + relu -> fp16 act smem
            #pragma unroll
            for (int ni = 0; ni < 2; ++ni) {
                const int col = n1 + ni * 8 + tig * 2;
                const float2 bia = *(const float2*)(bf1 + jb + col);
                const int row = m0 + gid;
                float a0 = fmaxf(acc1[ni][0] + bia.x, 0.f);
                float a1 = fmaxf(acc1[ni][1] + bia.y, 0.f);
                float a2 = fmaxf(acc1[ni][2] + bia.x, 0.f);
                float a3 = fmaxf(acc1[ni][3] + bia.y, 0.f);
                *(uint32_t*)(smem + G2_AC + (uint32_t)(row * SWN + col) * 2) =
                    pack_f16(a0, a1);
                *(uint32_t*)(smem + G2_AC + (uint32_t)((row + 8) * SWN + col) * 2) =
                    pack_f16(a2, a3);
            }
            __syncthreads();

            // GEMM2: acc2 += act @ W2chunk; warp: 16M x 32N, K=64
            const int n2 = wn * 32;
            #pragma unroll
            for (int kf = 0; kf < 4; ++kf) {
                const int k0 = kf * 16;
                uint32_t af[4], bq[2][4];
                {
                    uint32_t ro = (uint32_t)((m0 + lrow) * SWN + k0 + lcol) * 2;
                    ldsm4(af, sb + G2_AC + ro);
                }
                #pragma unroll
                for (int g = 0; g < 2; ++g) {
                    uint32_t ro = (uint32_t)((k0 + lrow) * SW2 + n2 + g * 16 + lcol) * 2;
                    ldsm4t(bq[g], sb + G2_W2(buf) + ro);
                }
                #pragma unroll
                for (int g = 0; g < 2; ++g)
                    #pragma unroll
                    for (int hh = 0; hh < 2; ++hh)
                        mma16816h(acc2[g * 2 + hh], af, &bq[g][hh * 2]);
            }
            __syncthreads();
        }

        // flush segment accumulator to its partial slot
        {
            const int n2 = wn * 32;
            float* base = partial + ((size_t)(2 * cta + seg) << 14);
            const int row = m0 + gid;
            #pragma unroll
            for (int nf = 0; nf < 4; ++nf) {
                const int col = n2 + nf * 8 + tig * 2;
                *(float2*)(base + row * E_ + col) =
                    make_float2(acc2[nf][0], acc2[nf][1]);
                *(float2*)(base + (row + 8) * E_ + col) =
                    make_float2(acc2[nf][2], acc2[nf][3]);
            }
        }
        seg++;
    }
}

// ---------------------------------------------------------------------------
// Final: out = x2 + bf2 + sum of covering partial slots
// ---------------------------------------------------------------------------
__global__ void k_final3(const float* __restrict__ x2, const float* __restrict__ partial,
                         const float* __restrict__ bf2, float* __restrict__ out) {
    int idx = blockIdx.x * blockDim.x + threadIdx.x;
    if (idx >= NTOK * E_) return;
    int e = idx & 127;
    int tok = idx >> 7;
    int t = tok >> 7;          // tile
    int row = tok & 127;

    // CTA range covering tile t (units [t*1024, (t+1)*1024), TOT2 = 2^15)
    int c_lo = (int)((((long long)t * 1024 + 1) * FFN_GRID - 1) >> 15);
    int c_hi = (int)((((long long)(t + 1) * 1024) * FFN_GRID - 1) >> 15);

    float s = x2[idx] + bf2[e];
    for (int c = c_lo; c <= c_hi; ++c) {
        int u0c = (int)(((long long)c << 15) / FFN_GRID);
        int seg = ((u0c >> 10) == t) ? 0 : 1;
        s += partial[((size_t)(2 * c + seg) << 14) + (row << 7) + e];
    }
    out[idx] = s;
}

// ---------------------------------------------------------------------------
// Launch
// ---------------------------------------------------------------------------
extern "C" void kernel_launch(void* const* d_in, const int* in_sizes, int n_in,
                              void* d_out, int out_size) {
    const float* x   = (const float*)d_in[0];
    const float* Wk  = (const float*)d_in[1];
    const float* Wq  = (const float*)d_in[2];
    const float* Wv  = (const float*)d_in[3];
    const float* Wo  = (const float*)d_in[4];
    const float* bo  = (const float*)d_in[5];
    const float* g1  = (const float*)d_in[6];
    const float* be1 = (const float*)d_in[7];
    const float* g2  = (const float*)d_in[8];
    const float* be2 = (const float*)d_in[9];
    const float* W1  = (const float*)d_in[10];
    const float* bf1 = (const float*)d_in[11];
    const float* W2  = (const float*)d_in[12];
    const float* bf2 = (const float*)d_in[13];
    float* out = (float*)d_out;

    float *pq, *pk, *pv, *px2, *ppart;
    __nv_bfloat16 *ph1hi, *ph1lo, *paohi, *paolo, *pwqhi, *pwqlo, *pwohi, *pwolo;
    __half *ph2f, *pw1f, *pw2f;
    cudaGetSymbolAddress((void**)&pq,    g_q);
    cudaGetSymbolAddress((void**)&pk,    g_k);
    cudaGetSymbolAddress((void**)&pv,    g_v);
    cudaGetSymbolAddress((void**)&px2,   g_x2);
    cudaGetSymbolAddress((void**)&ppart, g_part2);
    cudaGetSymbolAddress((void**)&ph1hi, g_h1hi);
    cudaGetSymbolAddress((void**)&ph1lo, g_h1lo);
    cudaGetSymbolAddress((void**)&paohi, g_aohi);
    cudaGetSymbolAddress((void**)&paolo, g_aolo);
    cudaGetSymbolAddress((void**)&ph2f,  g_h2f);
    cudaGetSymbolAddress((void**)&pw1f,  g_w1f);
    cudaGetSymbolAddress((void**)&pw2f,  g_w2f);
    cudaGetSymbolAddress((void**)&pwqhi, g_wqkvhi);
    cudaGetSymbolAddress((void**)&pwqlo, g_wqkvlo);
    cudaGetSymbolAddress((void**)&pwohi, g_wohi);
    cudaGetSymbolAddress((void**)&pwolo, g_wolo);

    cudaFuncSetAttribute(k_ffn3, cudaFuncAttributeMaxDynamicSharedMemorySize, FFN_SMEM3);
    cudaFuncSetAttribute(k_qkv_mma, cudaFuncAttributeMaxDynamicSharedMemorySize, QKV_SMEM);
    cudaFuncSetAttribute(k_oproj_mma, cudaFuncAttributeMaxDynamicSharedMemorySize, OP_SMEM);

    const int nW = E_ * HID_ / 4;
    k_cvthalf<<<(nW + 255) / 256, 256>>>(W1, pw1f, nW);
    k_cvthalf<<<(nW + 255) / 256, 256>>>(W2, pw2f, nW);
    k_cvt<<<(E_ * E_ / 4 + 255) / 256, 256>>>(Wo, pwohi, pwolo, E_ * E_ / 4);
    k_prep_wqkv<<<(E_ * 384 + 255) / 256, 256>>>(Wq, Wk, Wv, pwqhi, pwqlo);

    k_ln_split<<<NTOK / 4, 128>>>(x, g1, be1, ph1hi, ph1lo);
    k_qkv_mma<<<dim3(NTOK / 64, 3), 256, QKV_SMEM>>>(ph1hi, ph1lo, pwqhi, pwqlo, pq, pk, pv);
    k_attn2<<<dim3(8, 16), 256>>>(pq, pk, pv, paohi, paolo);
    k_oproj_mma<<<NTOK / 64, 256, OP_SMEM>>>(paohi, paolo, pwohi, pwolo, bo, x,
                                             g2, be2, px2, ph2f);
    k_ffn3<<<FFN_GRID, 1024, FFN_SMEM3>>>(ph2f, pw1f, pw2f, bf1, ppart);
    k_final3<<<(NTOK * E_ + 255) / 256, 256>>>(px2, ppart, bf2, out);
}

// round 13
// speedup vs baseline: 1.3611x; 1.3611x over previous
#include <cuda_runtime.h>
#include <cuda_bf16.h>
#include <cuda_fp16.h>
#include <cstdint>
#include <math.h>

// ---------------------------------------------------------------------------
// Problem constants
// ---------------------------------------------------------------------------
#define B_  2
#define T_  2048
#define E_  128
#define H_  8
#define HS_ 16
#define HID_ 65536
#define NTOK (B_ * T_)          // 4096
#define EPS_ 1e-5f
#define ATT_SCALE 0.08838834764831845f   // 1/sqrt(128)

// FFN tiling (1-pass fp16, JC=64, 256 threads, 2 CTAs/SM)
#define FFN_M 128
#define JC2 64
#define NCHUNK2 (HID_ / JC2)        // 1024 chunks per tile
#define NTILE (NTOK / FFN_M)        // 32
#define TOT2 (NTILE * NCHUNK2)      // 32768
#define FFN_GRID 888                // 3 waves at 2 CTAs/SM (296), 6 at 1

// padded smem strides (in halves); stride*2 bytes/16 must be odd for ldmatrix
#define SH   136   // h / generic 128-col tiles (17 x 16B)
#define SWN  72    // 64-col tiles: W1 chunk, act (9 x 16B)
#define SW2  136   // W2 chunk 128-col

// FFN smem byte offsets (W1 single-buffered, W2 double, act single)
#define G3_H 0                            // 128 x 136 x 2 = 34816
#define G3_W1 34816                       // 128 x 72 x 2 = 18432
#define G3_W2(b) (53248 + (b) * 17408)    // 64 x 136 x 2, x2
#define G3_AC 88064                       // 128 x 72 x 2 = 18432
#define FFN_SMEM4 106496

// QKV / OPROJ GEMM smem offsets (bf16 3-pass path, unchanged)
#define GA_HI 0
#define GA_LO 17408
#define GW_HI 34816
#define GW_LO 69632
#define QKV_SMEM 104448
#define OP_X2T  104448
#define OP_SMEM (104448 + 64 * 132 * 4)

// ---------------------------------------------------------------------------
// PTX helpers
// ---------------------------------------------------------------------------
__device__ __forceinline__ uint32_t smem_u32(const void* p) {
    uint32_t a;
    asm("{ .reg .u64 t; cvta.to.shared.u64 t, %1; cvt.u32.u64 %0, t; }"
        : "=r"(a) : "l"(p));
    return a;
}
__device__ __forceinline__ void ldsm4(uint32_t a[4], uint32_t addr) {
    asm volatile("ldmatrix.sync.aligned.m8n8.x4.shared.b16 {%0,%1,%2,%3}, [%4];"
                 : "=r"(a[0]), "=r"(a[1]), "=r"(a[2]), "=r"(a[3]) : "r"(addr));
}
__device__ __forceinline__ void ldsm4t(uint32_t a[4], uint32_t addr) {
    asm volatile("ldmatrix.sync.aligned.m8n8.x4.trans.shared.b16 {%0,%1,%2,%3}, [%4];"
                 : "=r"(a[0]), "=r"(a[1]), "=r"(a[2]), "=r"(a[3]) : "r"(addr));
}
__device__ __forceinline__ void mma16816(float c[4], const uint32_t a[4],
                                         const uint32_t b[2]) {
    asm volatile("mma.sync.aligned.m16n8k16.row.col.f32.bf16.bf16.f32 "
                 "{%0,%1,%2,%3}, {%4,%5,%6,%7}, {%8,%9}, {%0,%1,%2,%3};"
                 : "+f"(c[0]), "+f"(c[1]), "+f"(c[2]), "+f"(c[3])
                 : "r"(a[0]), "r"(a[1]), "r"(a[2]), "r"(a[3]),
                   "r"(b[0]), "r"(b[1]));
}
__device__ __forceinline__ void mma16816h(float c[4], const uint32_t a[4],
                                          const uint32_t b[2]) {
    asm volatile("mma.sync.aligned.m16n8k16.row.col.f32.f16.f16.f32 "
                 "{%0,%1,%2,%3}, {%4,%5,%6,%7}, {%8,%9}, {%0,%1,%2,%3};"
                 : "+f"(c[0]), "+f"(c[1]), "+f"(c[2]), "+f"(c[3])
                 : "r"(a[0]), "r"(a[1]), "r"(a[2]), "r"(a[3]),
                   "r"(b[0]), "r"(b[1]));
}
__device__ __forceinline__ void cp16(uint32_t s, const void* g) {
    asm volatile("cp.async.cg.shared.global [%0], [%1], 16;" :: "r"(s), "l"(g));
}
#define CP_COMMIT() asm volatile("cp.async.commit_group;" ::: "memory")
#define CP_WAIT1()  asm volatile("cp.async.wait_group 1;" ::: "memory")
#define CP_WAIT0()  asm volatile("cp.async.wait_group 0;" ::: "memory")

__device__ __forceinline__ uint32_t pack_bf16(float a, float b) {
    uint32_t ua = __bfloat16_as_ushort(__float2bfloat16(a));
    uint32_t ub = __bfloat16_as_ushort(__float2bfloat16(b));
    return ua | (ub << 16);
}
__device__ __forceinline__ uint32_t pack_f16(float a, float b) {
    __half2 h = __floats2half2_rn(a, b);
    return *reinterpret_cast<uint32_t*>(&h);
}

// ---------------------------------------------------------------------------
// Scratch
// ---------------------------------------------------------------------------
__device__ float g_q  [B_ * H_ * T_ * HS_];
__device__ float g_k  [B_ * H_ * T_ * HS_];
__device__ float g_v  [B_ * H_ * T_ * HS_];
__device__ float g_x2 [NTOK * E_];
__device__ float g_part2[2 * FFN_GRID * FFN_M * E_];   // 116 MB
__device__ __nv_bfloat16 g_h1hi[NTOK * E_];
__device__ __nv_bfloat16 g_h1lo[NTOK * E_];
__device__ __nv_bfloat16 g_aohi[NTOK * E_];
__device__ __nv_bfloat16 g_aolo[NTOK * E_];
__device__ __half g_h2f [NTOK * E_];
__device__ __half g_w1f [E_ * HID_];
__device__ __half g_w2f [HID_ * E_];
__device__ __nv_bfloat16 g_wqkvhi[E_ * 384];
__device__ __nv_bfloat16 g_wqkvlo[E_ * 384];
__device__ __nv_bfloat16 g_wohi[E_ * E_];
__device__ __nv_bfloat16 g_wolo[E_ * E_];

// ---------------------------------------------------------------------------
// fp32 -> bf16 hi/lo split (attention-path weights)
// ---------------------------------------------------------------------------
__global__ void k_cvt(const float* __restrict__ src,
                      __nv_bfloat16* __restrict__ hi,
                      __nv_bfloat16* __restrict__ lo, int n4) {
    int i = blockIdx.x * 256 + threadIdx.x;
    if (i >= n4) return;
    float4 v = ((const float4*)src)[i];
    __nv_bfloat16 h0 = __float2bfloat16(v.x), h1 = __float2bfloat16(v.y);
    __nv_bfloat16 h2 = __float2bfloat16(v.z), h3 = __float2bfloat16(v.w);
    uint2 ho, loo;
    ho.x = ((uint32_t)__bfloat16_as_ushort(h1) << 16) | __bfloat16_as_ushort(h0);
    ho.y = ((uint32_t)__bfloat16_as_ushort(h3) << 16) | __bfloat16_as_ushort(h2);
    loo.x = pack_bf16(v.x - __bfloat162float(h0), v.y - __bfloat162float(h1));
    loo.y = pack_bf16(v.z - __bfloat162float(h2), v.w - __bfloat162float(h3));
    ((uint2*)hi)[i] = ho;
    ((uint2*)lo)[i] = loo;
}

// fp32 -> fp16 plain convert (FFN weights)
__global__ void k_cvthalf(const float* __restrict__ src,
                          __half* __restrict__ dst, int n4) {
    int i = blockIdx.x * 256 + threadIdx.x;
    if (i >= n4) return;
    float4 v = ((const float4*)src)[i];
    uint2 o;
    o.x = pack_f16(v.x, v.y);
    o.y = pack_f16(v.z, v.w);
    ((uint2*)dst)[i] = o;
}

// Build Wqkv [E][384] bf16 hi/lo from Wq/Wk/Wv [H][E][HS]
__global__ void k_prep_wqkv(const float* __restrict__ Wq, const float* __restrict__ Wk,
                            const float* __restrict__ Wv,
                            __nv_bfloat16* __restrict__ ohi,
                            __nv_bfloat16* __restrict__ olo) {
    int idx = blockIdx.x * 256 + threadIdx.x;
    if (idx >= E_ * 384) return;
    int e = idx / 384, n = idx % 384;
    int which = n >> 7, r = n & 127, h = r >> 4, hd = r & 15;
    const float* W = (which == 0) ? Wq : (which == 1) ? Wk : Wv;
    float f = W[((size_t)h * E_ + e) * HS_ + hd];
    __nv_bfloat16 hh = __float2bfloat16(f);
    ohi[idx] = hh;
    olo[idx] = __float2bfloat16(f - __bfloat162float(hh));
}

// ---------------------------------------------------------------------------
// LayerNorm with bf16 hi/lo split output (LN1)
// ---------------------------------------------------------------------------
__global__ void k_ln_split(const float* __restrict__ x, const float* __restrict__ g,
                           const float* __restrict__ b,
                           __nv_bfloat16* __restrict__ ohi,
                           __nv_bfloat16* __restrict__ olo) {
    int t = blockIdx.x * 4 + (threadIdx.x >> 5);
    int lane = threadIdx.x & 31;
    float4 a = ((const float4*)(x + (size_t)t * E_))[lane];

    float s = a.x + a.y + a.z + a.w;
    #pragma unroll
    for (int o = 16; o; o >>= 1) s += __shfl_xor_sync(0xffffffffu, s, o);
    float mu = s * (1.0f / E_);

    float dx = a.x - mu, dy = a.y - mu, dz = a.z - mu, dw = a.w - mu;
    float v = dx*dx + dy*dy + dz*dz + dw*dw;
    #pragma unroll
    for (int o = 16; o; o >>= 1) v += __shfl_xor_sync(0xffffffffu, v, o);
    float rs = rsqrtf(v * (1.0f / E_) + EPS_);

    float4 gg = ((const float4*)g)[lane];
    float4 bb = ((const float4*)b)[lane];
    float r0 = dx * rs * gg.x + bb.x;
    float r1 = dy * rs * gg.y + bb.y;
    float r2 = dz * rs * gg.z + bb.z;
    float r3 = dw * rs * gg.w + bb.w;

    __nv_bfloat16 h0 = __float2bfloat16(r0), h1 = __float2bfloat16(r1);
    __nv_bfloat16 h2 = __float2bfloat16(r2), h3 = __float2bfloat16(r3);
    uint2 ho, loo;
    ho.x = ((uint32_t)__bfloat16_as_ushort(h1) << 16) | __bfloat16_as_ushort(h0);
    ho.y = ((uint32_t)__bfloat16_as_ushort(h3) << 16) | __bfloat16_as_ushort(h2);
    loo.x = pack_bf16(r0 - __bfloat162float(h0), r1 - __bfloat162float(h1));
    loo.y = pack_bf16(r2 - __bfloat162float(h2), r3 - __bfloat162float(h3));
    ((uint2*)(ohi + (size_t)t * E_))[lane] = ho;
    ((uint2*)(olo + (size_t)t * E_))[lane] = loo;
}

// ---------------------------------------------------------------------------
// QKV via mma (bf16 3-pass, unchanged)
// ---------------------------------------------------------------------------
__global__ void __launch_bounds__(256, 1)
k_qkv_mma(const __nv_bfloat16* __restrict__ ahi, const __nv_bfloat16* __restrict__ alo,
          const __nv_bfloat16* __restrict__ whi, const __nv_bfloat16* __restrict__ wlo,
          float* __restrict__ q, float* __restrict__ k, float* __restrict__ v) {
    extern __shared__ char smem[];
    const uint32_t sb = smem_u32(smem);
    const int tid = threadIdx.x, wid = tid >> 5, lane = tid & 31;
    const int gid = lane >> 2, tig = lane & 3;
    const int lrow = (lane & 7) + ((lane >> 3) & 1) * 8;
    const int lcol = ((lane >> 4) & 1) * 8;
    const int wm = wid & 1, wn = wid >> 1;
    const int tok0 = blockIdx.x * 64;
    const int slab = blockIdx.y;
    const int m0 = wm * 32, n0 = wn * 32;

    for (int i = tid; i < 1024; i += 256) {
        int r = i >> 4, s = i & 15;
        *(float4*)(smem + GA_HI + (r * SH + s * 8) * 2) =
            *(const float4*)(ahi + (size_t)(tok0 + r) * E_ + s * 8);
        *(float4*)(smem + GA_LO + (r * SH + s * 8) * 2) =
            *(const float4*)(alo + (size_t)(tok0 + r) * E_ + s * 8);
    }
    for (int i = tid; i < 2048; i += 256) {
        int r = i >> 4, s = i & 15;
        *(float4*)(smem + GW_HI + (r * SH + s * 8) * 2) =
            *(const float4*)(whi + (size_t)r * 384 + slab * 128 + s * 8);
        *(float4*)(smem + GW_LO + (r * SH + s * 8) * 2) =
            *(const float4*)(wlo + (size_t)r * 384 + slab * 128 + s * 8);
    }
    __syncthreads();

    float acc[2][4][4];
    #pragma unroll
    for (int a = 0; a < 2; ++a)
        #pragma unroll
        for (int b = 0; b < 4; ++b)
            #pragma unroll
            for (int c = 0; c < 4; ++c) acc[a][b][c] = 0.f;

    #pragma unroll
    for (int kf = 0; kf < 8; ++kf) {
        const int k0 = kf * 16;
        uint32_t ah[2][4], al[2][4], bh2[2][4], bl2[2][4];
        #pragma unroll
        for (int mi = 0; mi < 2; ++mi) {
            uint32_t ro = (uint32_t)((m0 + mi * 16 + lrow) * SH + k0 + lcol) * 2;
            ldsm4(ah[mi], sb + GA_HI + ro);
            ldsm4(al[mi], sb + GA_LO + ro);
        }
        #pragma unroll
        for (int g = 0; g < 2; ++g) {
            uint32_t ro = (uint32_t)((k0 + lrow) * SH + n0 + g * 16 + lcol) * 2;
            ldsm4t(bh2[g], sb + GW_HI + ro);
            ldsm4t(bl2[g], sb + GW_LO + ro);
        }
        #pragma unroll
        for (int mi = 0; mi < 2; ++mi)
            #pragma unroll
            for (int g = 0; g < 2; ++g)
                #pragma unroll
                for (int hh = 0; hh < 2; ++hh) {
                    float* a = acc[mi][g * 2 + hh];
                    mma16816(a, ah[mi], &bh2[g][hh * 2]);
                    mma16816(a, ah[mi], &bl2[g][hh * 2]);
                    mma16816(a, al[mi], &bh2[g][hh * 2]);
                }
    }

    float* dst = (slab == 0) ? q : (slab == 1) ? k : v;
    #pragma unroll
    for (int mi = 0; mi < 2; ++mi) {
        int tg = tok0 + m0 + mi * 16 + gid;
        int b = tg >> 11, tl = tg & 2047;
        #pragma unroll
        for (int ni = 0; ni < 4; ++ni) {
            int n = n0 + ni * 8 + tig * 2;
            int h = n >> 4, hd = n & 15;
            float* p = dst + (((size_t)(b * 8 + h)) * T_ + tl) * HS_ + hd;
            *(float2*)p = make_float2(acc[mi][ni][0], acc[mi][ni][1]);
            *(float2*)(p + 8 * HS_) = make_float2(acc[mi][ni][2], acc[mi][ni][3]);
        }
    }
}

// ---------------------------------------------------------------------------
// Attention (unchanged)
// ---------------------------------------------------------------------------
__global__ void __launch_bounds__(256, 1)
k_attn2(const float* __restrict__ q, const float* __restrict__ k,
        const float* __restrict__ v,
        __nv_bfloat16* __restrict__ aohi, __nv_bfloat16* __restrict__ aolo) {
    __shared__ float Ks[2][128][16];
    __shared__ float Vs[2][128][16];
    const int tid = threadIdx.x, wid = tid >> 5, lane = tid & 31;
    const int bh = blockIdx.y, qb = blockIdx.x;
    const int wg = wid >> 2;
    const int qblk = wg ? (15 - qb) : qb;
    const int t = qblk * 128 + (wid & 3) * 32 + lane;
    const int mytiles = qblk + 1;
    const int ntiles = 16 - qb;

    const float* qp = q + ((size_t)bh * T_ + t) * HS_;
    float4 q0 = ((const float4*)qp)[0];
    float4 q1 = ((const float4*)qp)[1];
    float4 q2 = ((const float4*)qp)[2];
    float4 q3 = ((const float4*)qp)[3];
    const float* kb_ = k + (size_t)bh * T_ * HS_;
    const float* vb_ = v + (size_t)bh * T_ * HS_;
    const uint32_t ksa = smem_u32(Ks), vsa = smem_u32(Vs);

    float m = -1e30f, l = 0.f;
    float o[16];
    #pragma unroll
    for (int d = 0; d < 16; ++d) o[d] = 0.f;

    #pragma unroll
    for (int i = 0; i < 2; ++i) {
        int f = tid + i * 256;
        int row = f >> 2, sg = f & 3;
        cp16(ksa + row * 64 + sg * 16, kb_ + (size_t)row * HS_ + sg * 4);
        cp16(vsa + row * 64 + sg * 16, vb_ + (size_t)row * HS_ + sg * 4);
    }
    CP_COMMIT();

    for (int it = 0; it < ntiles; ++it) {
        const int buf = it & 1;
        if (it + 1 < ntiles) {
            int kb2 = (it + 1) * 128;
            int ob = (buf ^ 1) * 8192;
            #pragma unroll
            for (int i = 0; i < 2; ++i) {
                int f = tid + i * 256;
                int row = f >> 2, sg = f & 3;
                cp16(ksa + ob + row * 64 + sg * 16, kb_ + (size_t)(kb2 + row) * HS_ + sg * 4);
                cp16(vsa + ob + row * 64 + sg * 16, vb_ + (size_t)(kb2 + row) * HS_ + sg * 4);
            }
        }
        CP_COMMIT();
        CP_WAIT1();
        __syncthreads();

        if (it < mytiles) {
            const int kbase = it * 128;
            #pragma unroll 2
            for (int j = 0; j < 128; ++j) {
                const float4* kr = (const float4*)&Ks[buf][j][0];
                float4 k0 = kr[0], k1 = kr[1], k2 = kr[2], k3 = kr[3];
                float sc = q0.x*k0.x + q0.y*k0.y + q0.z*k0.z + q0.w*k0.w
                         + q1.x*k1.x + q1.y*k1.y + q1.z*k1.z + q1.w*k1.w
                         + q2.x*k2.x + q2.y*k2.y + q2.z*k2.z + q2.w*k2.w
                         + q3.x*k3.x + q3.y*k3.y + q3.z*k3.z + q3.w*k3.w;
                sc *= ATT_SCALE;
                if (kbase + j > t) sc = -1e30f;
                float mn = fmaxf(m, sc);
                float scale = __expf(m - mn);
                float w = __expf(sc - mn);
                l = l * scale + w;
                const float4* vr = (const float4*)&Vs[buf][j][0];
                float4 v0 = vr[0], v1 = vr[1], v2 = vr[2], v3 = vr[3];
                o[0]  = o[0]*scale  + w*v0.x;  o[1]  = o[1]*scale  + w*v0.y;
                o[2]  = o[2]*scale  + w*v0.z;  o[3]  = o[3]*scale  + w*v0.w;
                o[4]  = o[4]*scale  + w*v1.x;  o[5]  = o[5]*scale  + w*v1.y;
                o[6]  = o[6]*scale  + w*v1.z;  o[7]  = o[7]*scale  + w*v1.w;
                o[8]  = o[8]*scale  + w*v2.x;  o[9]  = o[9]*scale  + w*v2.y;
                o[10] = o[10]*scale + w*v2.z;  o[11] = o[11]*scale + w*v2.w;
                o[12] = o[12]*scale + w*v3.x;  o[13] = o[13]*scale + w*v3.y;
                o[14] = o[14]*scale + w*v3.z;  o[15] = o[15]*scale + w*v3.w;
                m = mn;
            }
        }
        __syncthreads();
    }

    float inv = 1.0f / l;
    int b = bh >> 3, h = bh & 7;
    size_t base = ((size_t)b * T_ + t) * E_ + h * HS_;
    uint32_t hi[8], lo[8];
    #pragma unroll
    for (int d = 0; d < 8; ++d) {
        float f0 = o[2 * d] * inv, f1 = o[2 * d + 1] * inv;
        __nv_bfloat16 h0 = __float2bfloat16(f0), h1 = __float2bfloat16(f1);
        hi[d] = ((uint32_t)__bfloat16_as_ushort(h1) << 16) | __bfloat16_as_ushort(h0);
        lo[d] = pack_bf16(f0 - __bfloat162float(h0), f1 - __bfloat162float(h1));
    }
    ((uint4*)(aohi + base))[0] = make_uint4(hi[0], hi[1], hi[2], hi[3]);
    ((uint4*)(aohi + base))[1] = make_uint4(hi[4], hi[5], hi[6], hi[7]);
    ((uint4*)(aolo + base))[0] = make_uint4(lo[0], lo[1], lo[2], lo[3]);
    ((uint4*)(aolo + base))[1] = make_uint4(lo[4], lo[5], lo[6], lo[7]);
}

// ---------------------------------------------------------------------------
// O-proj via mma + residual + fused LN2 (h2 fp16 out)
// ---------------------------------------------------------------------------
__global__ void __launch_bounds__(256, 1)
k_oproj_mma(const __nv_bfloat16* __restrict__ ahi, const __nv_bfloat16* __restrict__ alo,
            const __nv_bfloat16* __restrict__ whi, const __nv_bfloat16* __restrict__ wlo,
            const float* __restrict__ bo, const float* __restrict__ x,
            const float* __restrict__ g2, const float* __restrict__ be2,
            float* __restrict__ x2, __half* __restrict__ h2f) {
    extern __shared__ char smem[];
    const uint32_t sb = smem_u32(smem);
    float* x2t = (float*)(smem + OP_X2T);
    const int tid = threadIdx.x, wid = tid >> 5, lane = tid & 31;
    const int gid = lane >> 2, tig = lane & 3;
    const int lrow = (lane & 7) + ((lane >> 3) & 1) * 8;
    const int lcol = ((lane >> 4) & 1) * 8;
    const int wm = wid & 1, wn = wid >> 1;
    const int tok0 = blockIdx.x * 64;
    const int m0 = wm * 32, n0 = wn * 32;

    for (int i = tid; i < 1024; i += 256) {
        int r = i >> 4, s = i & 15;
        *(float4*)(smem + GA_HI + (r * SH + s * 8) * 2) =
            *(const float4*)(ahi + (size_t)(tok0 + r) * E_ + s * 8);
        *(float4*)(smem + GA_LO + (r * SH + s * 8) * 2) =
            *(const float4*)(alo + (size_t)(tok0 + r) * E_ + s * 8);
    }
    for (int i = tid; i < 2048; i += 256) {
        int r = i >> 4, s = i & 15;
        *(float4*)(smem + GW_HI + (r * SH + s * 8) * 2) =
            *(const float4*)(whi + (size_t)r * E_ + s * 8);
        *(float4*)(smem + GW_LO + (r * SH + s * 8) * 2) =
            *(const float4*)(wlo + (size_t)r * E_ + s * 8);
    }
    __syncthreads();

    float acc[2][4][4];
    #pragma unroll
    for (int a = 0; a < 2; ++a)
        #pragma unroll
        for (int b = 0; b < 4; ++b)
            #pragma unroll
            for (int c = 0; c < 4; ++c) acc[a][b][c] = 0.f;

    #pragma unroll
    for (int kf = 0; kf < 8; ++kf) {
        const int k0 = kf * 16;
        uint32_t ah[2][4], al[2][4], bh2[2][4], bl2[2][4];
        #pragma unroll
        for (int mi = 0; mi < 2; ++mi) {
            uint32_t ro = (uint32_t)((m0 + mi * 16 + lrow) * SH + k0 + lcol) * 2;
            ldsm4(ah[mi], sb + GA_HI + ro);
            ldsm4(al[mi], sb + GA_LO + ro);
        }
        #pragma unroll
        for (int g = 0; g < 2; ++g) {
            uint32_t ro = (uint32_t)((k0 + lrow) * SH + n0 + g * 16 + lcol) * 2;
            ldsm4t(bh2[g], sb + GW_HI + ro);
            ldsm4t(bl2[g], sb + GW_LO + ro);
        }
        #pragma unroll
        for (int mi = 0; mi < 2; ++mi)
            #pragma unroll
            for (int g = 0; g < 2; ++g)
                #pragma unroll
                for (int hh = 0; hh < 2; ++hh) {
                    float* a = acc[mi][g * 2 + hh];
                    mma16816(a, ah[mi], &bh2[g][hh * 2]);
                    mma16816(a, ah[mi], &bl2[g][hh * 2]);
                    mma16816(a, al[mi], &bh2[g][hh * 2]);
                }
    }

    #pragma unroll
    for (int mi = 0; mi < 2; ++mi) {
        int rl = m0 + mi * 16 + gid;
        #pragma unroll
        for (int ni = 0; ni < 4; ++ni) {
            int col = n0 + ni * 8 + tig * 2;
            float2 bia = *(const float2*)(bo + col);
            float2 xr0 = *(const float2*)(x + (size_t)(tok0 + rl) * E_ + col);
            float2 xr1 = *(const float2*)(x + (size_t)(tok0 + rl + 8) * E_ + col);
            x2t[rl * 132 + col]           = acc[mi][ni][0] + bia.x + xr0.x;
            x2t[rl * 132 + col + 1]       = acc[mi][ni][1] + bia.y + xr0.y;
            x2t[(rl + 8) * 132 + col]     = acc[mi][ni][2] + bia.x + xr1.x;
            x2t[(rl + 8) * 132 + col + 1] = acc[mi][ni][3] + bia.y + xr1.y;
        }
    }
    __syncthreads();

    float4 gg = ((const float4*)g2)[lane];
    float4 bb = ((const float4*)be2)[lane];
    #pragma unroll
    for (int r = 0; r < 8; ++r) {
        int tokl = wid * 8 + r;
        float4 a = *(float4*)(x2t + tokl * 132 + lane * 4);
        float s = a.x + a.y + a.z + a.w;
        #pragma unroll
        for (int o = 16; o; o >>= 1) s += __shfl_xor_sync(0xffffffffu, s, o);
        float mu = s * (1.0f / E_);
        float dx = a.x - mu, dy = a.y - mu, dz = a.z - mu, dw = a.w - mu;
        float vv = dx*dx + dy*dy + dz*dz + dw*dw;
        #pragma unroll
        for (int o = 16; o; o >>= 1) vv += __shfl_xor_sync(0xffffffffu, vv, o);
        float rs = rsqrtf(vv * (1.0f / E_) + EPS_);

        ((float4*)(x2 + (size_t)(tok0 + tokl) * E_))[lane] = a;

        float r0 = dx * rs * gg.x + bb.x;
        float r1 = dy * rs * gg.y + bb.y;
        float r2 = dz * rs * gg.z + bb.z;
        float r3 = dw * rs * gg.w + bb.w;
        uint2 hp;
        hp.x = pack_f16(r0, r1);
        hp.y = pack_f16(r2, r3);
        ((uint2*)(h2f + (size_t)(tok0 + tokl) * E_))[lane] = hp;
    }
}

// ---------------------------------------------------------------------------
// FFN fp16 1-pass, JC=64, 256 threads, 2 CTAs/SM, W1 single-buffered.
// Warp grid 4 wm x 2 wn: GEMM1 32M x 32N, GEMM2 32M x 64N.
// ---------------------------------------------------------------------------
__global__ void __launch_bounds__(256, 2)
k_ffn4(const __half* __restrict__ h2,
       const __half* __restrict__ w1, const __half* __restrict__ w2,
       const float* __restrict__ bf1, float* __restrict__ partial) {
    extern __shared__ char smem[];
    const uint32_t sb = smem_u32(smem);
    const int tid = threadIdx.x, wid = tid >> 5, lane = tid & 31;
    const int gid = lane >> 2, tig = lane & 3;
    const int lrow = (lane & 7) + ((lane >> 3) & 1) * 8;
    const int lcol = ((lane >> 4) & 1) * 8;
    const int wm = wid & 3, wn = wid >> 2;   // 4 x 2 warp grid
    const int m0 = wm * 32;
    const int cta = blockIdx.x;
    const int u0 = (int)(((long long)cta * TOT2) / FFN_GRID);
    const int u1 = (int)(((long long)(cta + 1) * TOT2) / FFN_GRID);

    // prefetch W1(u0) + W2(u0) -> group 0
    {
        int jb = (u0 & (NCHUNK2 - 1)) * JC2;
        #pragma unroll
        for (int i = 0; i < 4; ++i) {
            int t = tid + i * 256;
            int e = t >> 3, sg = t & 7;
            cp16(sb + G3_W1 + (e * SWN + sg * 8) * 2, w1 + (size_t)e * HID_ + jb + sg * 8);
            int j = t >> 4, sg2 = t & 15;
            cp16(sb + G3_W2(0) + (j * SW2 + sg2 * 8) * 2, w2 + (size_t)(jb + j) * E_ + sg2 * 8);
        }
    }
    CP_COMMIT();

    int u = u0, seg = 0;
    while (u < u1) {
        const int tile = u >> 10;
        const int useg_end = min(u1, (tile + 1) << 10);
        const int tok0 = tile * FFN_M;

        // load h tile (fp16)
        for (int i = tid; i < 2048; i += 256) {
            int r = i >> 4, s = i & 15;
            *(float4*)(smem + G3_H + (r * SH + s * 8) * 2) =
                *(const float4*)(h2 + (size_t)(tok0 + r) * E_ + s * 8);
        }
        float acc2[2][8][4];
        #pragma unroll
        for (int a = 0; a < 2; ++a)
            #pragma unroll
            for (int b = 0; b < 8; ++b)
                #pragma unroll
                for (int c = 0; c < 4; ++c) acc2[a][b][c] = 0.f;
        __syncthreads();

        for (; u < useg_end; ++u) {
            const int buf = (u - u0) & 1;
            const int jb = (u & (NCHUNK2 - 1)) * JC2;
            const bool more = (u + 1 < u1);

            // prefetch W2(u+1) into other buffer
            if (more) {
                int jn = ((u + 1) & (NCHUNK2 - 1)) * JC2;
                #pragma unroll
                for (int i = 0; i < 4; ++i) {
                    int t = tid + i * 256;
                    int j = t >> 4, sg2 = t & 15;
                    cp16(sb + G3_W2(buf ^ 1) + (j * SW2 + sg2 * 8) * 2,
                         w2 + (size_t)(jn + j) * E_ + sg2 * 8);
                }
                CP_COMMIT();
                CP_WAIT1();      // completes W1(u), W2(u)
            } else {
                CP_WAIT0();
            }
            __syncthreads();

            // GEMM1: act[128][64] = relu(h @ W1chunk + b1); warp: 32M x 32N
            const int n1 = wn * 32;
            float acc1[2][4][4];
            #pragma unroll
            for (int a = 0; a < 2; ++a)
                #pragma unroll
                for (int b = 0; b < 4; ++b)
                    #pragma unroll
                    for (int d = 0; d < 4; ++d) acc1[a][b][d] = 0.f;

            #pragma unroll
            for (int kf = 0; kf < 8; ++kf) {
                const int k0 = kf * 16;
                uint32_t af[2][4], bq[2][4];
                #pragma unroll
                for (int mi = 0; mi < 2; ++mi) {
                    uint32_t ro = (uint32_t)((m0 + mi * 16 + lrow) * SH + k0 + lcol) * 2;
                    ldsm4(af[mi], sb + G3_H + ro);
                }
                #pragma unroll
                for (int g = 0; g < 2; ++g) {
                    uint32_t ro = (uint32_t)((k0 + lrow) * SWN + n1 + g * 16 + lcol) * 2;
                    ldsm4t(bq[g], sb + G3_W1 + ro);
                }
                #pragma unroll
                for (int mi = 0; mi < 2; ++mi)
                    #pragma unroll
                    for (int g = 0; g < 2; ++g)
                        #pragma unroll
                        for (int hh = 0; hh < 2; ++hh)
                            mma16816h(acc1[mi][g * 2 + hh], af[mi], &bq[g][hh * 2]);
            }

            // epilogue: bias + relu -> fp16 act smem
            #pragma unroll
            for (int ni = 0; ni < 4; ++ni) {
                const int col = n1 + ni * 8 + tig * 2;
                const float2 bia = *(const float2*)(bf1 + jb + col);
                #pragma unroll
                for (int mi = 0; mi < 2; ++mi) {
                    const int row = m0 + mi * 16 + gid;
                    float a0 = fmaxf(acc1[mi][ni][0] + bia.x, 0.f);
                    float a1 = fmaxf(acc1[mi][ni][1] + bia.y, 0.f);
                    float a2 = fmaxf(acc1[mi][ni][2] + bia.x, 0.f);
                    float a3 = fmaxf(acc1[mi][ni][3] + bia.y, 0.f);
                    *(uint32_t*)(smem + G3_AC + (uint32_t)(row * SWN + col) * 2) =
                        pack_f16(a0, a1);
                    *(uint32_t*)(smem + G3_AC + (uint32_t)((row + 8) * SWN + col) * 2) =
                        pack_f16(a2, a3);
                }
            }
            __syncthreads();   // act ready; GEMM1 reads of W1 done

            // prefetch W1(u+1) into the single W1 buffer (hidden under GEMM2)
            if (more) {
                int jn = ((u + 1) & (NCHUNK2 - 1)) * JC2;
                #pragma unroll
                for (int i = 0; i < 4; ++i) {
                    int t = tid + i * 256;
                    int e = t >> 3, sg = t & 7;
                    cp16(sb + G3_W1 + (e * SWN + sg * 8) * 2,
                         w1 + (size_t)e * HID_ + jn + sg * 8);
                }
                CP_COMMIT();
            }

            // GEMM2: acc2 += act @ W2chunk; warp: 32M x 64N, K=64
            const int n2 = wn * 64;
            #pragma unroll
            for (int kf = 0; kf < 4; ++kf) {
                const int k0 = kf * 16;
                uint32_t af[2][4], bq[4][4];
                #pragma unroll
                for (int mi = 0; mi < 2; ++mi) {
                    uint32_t ro = (uint32_t)((m0 + mi * 16 + lrow) * SWN + k0 + lcol) * 2;
                    ldsm4(af[mi], sb + G3_AC + ro);
                }
                #pragma unroll
                for (int nj = 0; nj < 4; ++nj) {
                    uint32_t ro = (uint32_t)((k0 + lrow) * SW2 + n2 + nj * 16 + lcol) * 2;
                    ldsm4t(bq[nj], sb + G3_W2(buf) + ro);
                }
                #pragma unroll
                for (int mi = 0; mi < 2; ++mi)
                    #pragma unroll
                    for (int nj = 0; nj < 4; ++nj)
                        #pragma unroll
                        for (int hh = 0; hh < 2; ++hh)
                            mma16816h(acc2[mi][nj * 2 + hh], af[mi], &bq[nj][hh * 2]);
            }
            __syncthreads();   // GEMM2 reads done (act + W2 buf reuse safe)
        }

        // flush segment accumulator to its partial slot
        {
            const int n2 = wn * 64;
            float* base = partial + ((size_t)(2 * cta + seg) << 14);
            #pragma unroll
            for (int mi = 0; mi < 2; ++mi) {
                const int row = m0 + mi * 16 + gid;
                #pragma unroll
                for (int nf = 0; nf < 8; ++nf) {
                    const int col = n2 + nf * 8 + tig * 2;
                    *(float2*)(base + row * E_ + col) =
                        make_float2(acc2[mi][nf][0], acc2[mi][nf][1]);
                    *(float2*)(base + (row + 8) * E_ + col) =
                        make_float2(acc2[mi][nf][2], acc2[mi][nf][3]);
                }
            }
        }
        seg++;
    }
}

// ---------------------------------------------------------------------------
// Final: out = x2 + bf2 + sum of covering partial slots
// ---------------------------------------------------------------------------
__global__ void k_final3(const float* __restrict__ x2, const float* __restrict__ partial,
                         const float* __restrict__ bf2, float* __restrict__ out) {
    int idx = blockIdx.x * blockDim.x + threadIdx.x;
    if (idx >= NTOK * E_) return;
    int e = idx & 127;
    int tok = idx >> 7;
    int t = tok >> 7;          // tile
    int row = tok & 127;

    // CTA range covering tile t (units [t*1024, (t+1)*1024), TOT2 = 2^15)
    int c_lo = (int)((((long long)t * 1024 + 1) * FFN_GRID - 1) >> 15);
    int c_hi = (int)((((long long)(t + 1) * 1024) * FFN_GRID - 1) >> 15);

    float s = x2[idx] + bf2[e];
    for (int c = c_lo; c <= c_hi; ++c) {
        int u0c = (int)(((long long)c << 15) / FFN_GRID);
        int seg = ((u0c >> 10) == t) ? 0 : 1;
        s += partial[((size_t)(2 * c + seg) << 14) + (row << 7) + e];
    }
    out[idx] = s;
}

// ---------------------------------------------------------------------------
// Launch
// ---------------------------------------------------------------------------
extern "C" void kernel_launch(void* const* d_in, const int* in_sizes, int n_in,
                              void* d_out, int out_size) {
    const float* x   = (const float*)d_in[0];
    const float* Wk  = (const float*)d_in[1];
    const float* Wq  = (const float*)d_in[2];
    const float* Wv  = (const float*)d_in[3];
    const float* Wo  = (const float*)d_in[4];
    const float* bo  = (const float*)d_in[5];
    const float* g1  = (const float*)d_in[6];
    const float* be1 = (const float*)d_in[7];
    const float* g2  = (const float*)d_in[8];
    const float* be2 = (const float*)d_in[9];
    const float* W1  = (const float*)d_in[10];
    const float* bf1 = (const float*)d_in[11];
    const float* W2  = (const float*)d_in[12];
    const float* bf2 = (const float*)d_in[13];
    float* out = (float*)d_out;

    float *pq, *pk, *pv, *px2, *ppart;
    __nv_bfloat16 *ph1hi, *ph1lo, *paohi, *paolo, *pwqhi, *pwqlo, *pwohi, *pwolo;
    __half *ph2f, *pw1f, *pw2f;
    cudaGetSymbolAddress((void**)&pq,    g_q);
    cudaGetSymbolAddress((void**)&pk,    g_k);
    cudaGetSymbolAddress((void**)&pv,    g_v);
    cudaGetSymbolAddress((void**)&px2,   g_x2);
    cudaGetSymbolAddress((void**)&ppart, g_part2);
    cudaGetSymbolAddress((void**)&ph1hi, g_h1hi);
    cudaGetSymbolAddress((void**)&ph1lo, g_h1lo);
    cudaGetSymbolAddress((void**)&paohi, g_aohi);
    cudaGetSymbolAddress((void**)&paolo, g_aolo);
    cudaGetSymbolAddress((void**)&ph2f,  g_h2f);
    cudaGetSymbolAddress((void**)&pw1f,  g_w1f);
    cudaGetSymbolAddress((void**)&pw2f,  g_w2f);
    cudaGetSymbolAddress((void**)&pwqhi, g_wqkvhi);
    cudaGetSymbolAddress((void**)&pwqlo, g_wqkvlo);
    cudaGetSymbolAddress((void**)&pwohi, g_wohi);
    cudaGetSymbolAddress((void**)&pwolo, g_wolo);

    cudaFuncSetAttribute(k_ffn4, cudaFuncAttributeMaxDynamicSharedMemorySize, FFN_SMEM4);
    cudaFuncSetAttribute(k_qkv_mma, cudaFuncAttributeMaxDynamicSharedMemorySize, QKV_SMEM);
    cudaFuncSetAttribute(k_oproj_mma, cudaFuncAttributeMaxDynamicSharedMemorySize, OP_SMEM);

    const int nW = E_ * HID_ / 4;
    k_cvthalf<<<(nW + 255) / 256, 256>>>(W1, pw1f, nW);
    k_cvthalf<<<(nW + 255) / 256, 256>>>(W2, pw2f, nW);
    k_cvt<<<(E_ * E_ / 4 + 255) / 256, 256>>>(Wo, pwohi, pwolo, E_ * E_ / 4);
    k_prep_wqkv<<<(E_ * 384 + 255) / 256, 256>>>(Wq, Wk, Wv, pwqhi, pwqlo);

    k_ln_split<<<NTOK / 4, 128>>>(x, g1, be1, ph1hi, ph1lo);
    k_qkv_mma<<<dim3(NTOK / 64, 3), 256, QKV_SMEM>>>(ph1hi, ph1lo, pwqhi, pwqlo, pq, pk, pv);
    k_attn2<<<dim3(8, 16), 256>>>(pq, pk, pv, paohi, paolo);
    k_oproj_mma<<<NTOK / 64, 256, OP_SMEM>>>(paohi, paolo, pwohi, pwolo, bo, x,
                                             g2, be2, px2, ph2f);
    k_ffn4<<<FFN_GRID, 256, FFN_SMEM4>>>(ph2f, pw1f, pw2f, bf1, ppart);
    k_final3<<<(NTOK * E_ + 255) / 256, 256>>>(px2, ppart, bf2, out);
}